// round 15
// baseline (speedup 1.0000x reference)
#include <cuda_runtime.h>
#include <cuda_bf16.h>
#include <cuda_fp16.h>
#include <cstdint>

// Problem constants (fixed by the dataset): N=30000, C=3, D=128, K=10, H=64
#define DD   128
#define HH   64
#define GATE 256   // 4*H per direction
#define ROW  512   // both directions of gate pre-activations

#define NMAX 30000

// Scratch (static device globals — allocation-free rule)
// gx pre-activations stored as fp16 (halves gather + C-write traffic).
__device__ __align__(16) unsigned short g_gxc[(size_t)3 * NMAX * 3 * ROW]; // 3 content slabs (rows n*3+t)
__device__ __align__(16) unsigned short g_gxn[(size_t)3 * NMAX * ROW];     // neighbor preacts per s
__device__ __align__(16) float g_content[(size_t)3 * NMAX * DD];           // content embeddings
__device__ __align__(16) float g_neigh[(size_t)9 * NMAX * DD];             // neigh[d][s][n][128]

// Fragment-native split-bf16 input weights + fused biases (4 sets)
__device__ __align__(16) uint32_t g_bp[4][65536];
__device__ float g_bsum[4][512];

__device__ __forceinline__ float sigm(float x) { return __fdividef(1.f, 1.f + __expf(-x)); }
__device__ __forceinline__ float tanh_(float x) { return 2.f * __fdividef(1.f, 1.f + __expf(-2.f * x)) - 1.f; }

__device__ __forceinline__ uint32_t smem_u32(const void* p) {
    uint32_t a;
    asm("{ .reg .u64 t; cvta.to.shared.u64 t, %1; cvt.u32.u64 %0, t; }" : "=r"(a) : "l"(p));
    return a;
}

// warp-level bf16 MMA  D(16x8,f32) += A(16x16,bf16 row) * B(16x8,bf16 col)
__device__ __forceinline__ void mma16816(float& f0, float& f1, float& f2, float& f3,
                                         const uint32_t* a, const uint32_t* b) {
    asm volatile(
        "mma.sync.aligned.m16n8k16.row.col.f32.bf16.bf16.f32 "
        "{%0,%1,%2,%3}, {%4,%5,%6,%7}, {%8,%9}, {%0,%1,%2,%3};"
        : "+f"(f0), "+f"(f1), "+f"(f2), "+f"(f3)
        : "r"(a[0]), "r"(a[1]), "r"(a[2]), "r"(a[3]), "r"(b[0]), "r"(b[1]));
}
__device__ __forceinline__ void ldmx4(uint32_t* r, uint32_t addr) {
    asm volatile("ldmatrix.sync.aligned.m8n8.x4.shared.b16 {%0,%1,%2,%3}, [%4];"
        : "=r"(r[0]), "=r"(r[1]), "=r"(r[2]), "=r"(r[3]) : "r"(addr));
}

__device__ __forceinline__ uint32_t pack_hi(float x, float y, float& rx, float& ry) {
    __nv_bfloat16 hx = __float2bfloat16_rn(x);
    __nv_bfloat16 hy = __float2bfloat16_rn(y);
    rx = x - __bfloat162float(hx);
    ry = y - __bfloat162float(hy);
    return ((uint32_t)__bfloat16_as_ushort(hy) << 16) | (uint32_t)__bfloat16_as_ushort(hx);
}
__device__ __forceinline__ uint32_t pack_bf(float x, float y) {
    return ((uint32_t)__bfloat16_as_ushort(__float2bfloat16_rn(y)) << 16)
         | (uint32_t)__bfloat16_as_ushort(__float2bfloat16_rn(x));
}

// ---------------------------------------------------------------------------
// Weight prep (R14): 4 input-projection sets [512][128] fp32 -> fragment-native
// split-bf16, biases fused.  blockIdx.x = set.
// ---------------------------------------------------------------------------
__global__ void prep_weights(const float* __restrict__ Wc,
                             const float* __restrict__ b1c, const float* __restrict__ b2c,
                             const float* __restrict__ Wn,
                             const float* __restrict__ b1n, const float* __restrict__ b2n)
{
    const int set = blockIdx.x;
    const float* W  = (set == 0) ? Wc : (Wn + (size_t)(set - 1) * 512 * 128);
    const float* b1 = (set == 0) ? b1c : (b1n + (size_t)(set - 1) * 512);
    const float* b2 = (set == 0) ? b2c : (b2n + (size_t)(set - 1) * 512);

    for (int i = threadIdx.x; i < 32768; i += blockDim.x) {
        int r    = i & 1;
        int nt   = (i >> 1) & 7;
        int lane = (i >> 4) & 31;
        int kt   = (i >> 9) & 7;
        int nb   = (i >> 12) & 7;
        int j = nb * 64 + nt * 8 + (lane >> 2);
        int k = kt * 16 + ((lane & 3) << 1) + r * 8;
        float w0 = W[(size_t)j * 128 + k];
        float w1 = W[(size_t)j * 128 + k + 1];
        float l0, l1;
        uint32_t hi = pack_hi(w0, w1, l0, l1);
        uint32_t lo = pack_bf(l0, l1);
        uint32_t base = (uint32_t)((nb * 8 + kt) * 32 + lane) * 32;
        g_bp[set][base + nt * 2 + r]      = hi;
        g_bp[set][base + 16 + nt * 2 + r] = lo;
    }
    for (int j = threadIdx.x; j < 512; j += blockDim.x)
        g_bsum[set][j] = b1[j] + b2[j];
}

// ---------------------------------------------------------------------------
// Tensor-core GEMM (R14, fp16 output): C[m][j] = sum_k A[m][k]*W[j][k] + bsum[j]
// ---------------------------------------------------------------------------
#define APITCH 272
#define ATILE  (64 * APITCH)
#define GT_SMEM (2 * ATILE)

__global__ __launch_bounds__(256, 2) void gemm_tc(
    const float* __restrict__ A, const uint32_t* __restrict__ Bp,
    const float* __restrict__ bsum, __half* __restrict__ C, int M)
{
    extern __shared__ char smc[];
    const uint32_t sb = smem_u32(smc);
    const int tid = threadIdx.x;
    const int lane = tid & 31, w = tid >> 5;
    const int row0 = blockIdx.x * 64;

    for (int q = tid; q < 64 * 32; q += 256) {
        int r = q >> 5;
        int kc = (q & 31) << 2;
        int gm = row0 + r;
        float4 v = make_float4(0.f, 0.f, 0.f, 0.f);
        if (gm < M) v = *(const float4*)(A + (size_t)gm * 128 + kc);
        float lx, ly, lz, lw;
        uint32_t h01 = pack_hi(v.x, v.y, lx, ly);
        uint32_t h23 = pack_hi(v.z, v.w, lz, lw);
        uint32_t l01 = pack_bf(lx, ly);
        uint32_t l23 = pack_bf(lz, lw);
        char* pr = smc + r * APITCH + kc * 2;
        *(uint2*)(pr)         = make_uint2(h01, h23);
        *(uint2*)(pr + ATILE) = make_uint2(l01, l23);
    }
    __syncthreads();

    const int cq = (lane & 3) << 1;
    const int rq = lane >> 2;
    float2 bv[8];
#pragma unroll
    for (int nt = 0; nt < 8; nt++)
        bv[nt] = *(const float2*)(bsum + w * 64 + nt * 8 + cq);

    const int gA = lane >> 3, rA = lane & 7;
    const int arow = ((gA & 1) << 3) + rA;
    const int acol = (gA >> 1) << 4;
    const uint32_t abase0 = sb + (uint32_t)arow * APITCH + acol;

    const uint32_t* bpw = Bp + (uint32_t)w * (8 * 32 * 32);

#pragma unroll
    for (int mt = 0; mt < 4; mt++) {
        float acc[8][4];
#pragma unroll
        for (int nt = 0; nt < 8; nt++) {
            acc[nt][0] = bv[nt].x; acc[nt][1] = bv[nt].y;
            acc[nt][2] = bv[nt].x; acc[nt][3] = bv[nt].y;
        }

#pragma unroll
        for (int kt = 0; kt < 8; kt++) {
            uint32_t bfr[32];
            const uint32_t* bp = bpw + (uint32_t)(kt * 32 + lane) * 32;
#pragma unroll
            for (int q = 0; q < 8; q++)
                *(uint4*)&bfr[q * 4] = *(const uint4*)(bp + q * 4);

            const uint32_t ab = abase0 + (uint32_t)(mt * 16) * APITCH + kt * 32;
            uint32_t af[4];
            ldmx4(af, ab);
#pragma unroll
            for (int nt = 0; nt < 8; nt++) {
                mma16816(acc[nt][0], acc[nt][1], acc[nt][2], acc[nt][3], af, &bfr[nt * 2]);
                mma16816(acc[nt][0], acc[nt][1], acc[nt][2], acc[nt][3], af, &bfr[16 + nt * 2]);
            }
            ldmx4(af, ab + ATILE);
#pragma unroll
            for (int nt = 0; nt < 8; nt++)
                mma16816(acc[nt][0], acc[nt][1], acc[nt][2], acc[nt][3], af, &bfr[nt * 2]);
        }

        const int m0 = row0 + mt * 16 + rq;
        const int m1 = m0 + 8;
#pragma unroll
        for (int nt = 0; nt < 8; nt++) {
            const int c0 = w * 64 + nt * 8 + cq;
            if (m0 < M)
                *(__half2*)(C + (size_t)m0 * ROW + c0) = __floats2half2_rn(acc[nt][0], acc[nt][1]);
            if (m1 < M)
                *(__half2*)(C + (size_t)m1 * ROW + c0) = __floats2half2_rn(acc[nt][2], acc[nt][3]);
        }
    }
}

// ---------------------------------------------------------------------------
// Bi-LSTM recurrence on warp MMAs (split-bf16 hi/lo, fp32 accum), v4:
//   - gx in fp16; each timestep's 64 gathered rows staged cooperatively into
//     SMEM (512B coalesced row loads), pitch 264 halves -> conflict-free reads
//   - content mode (nbr==null): blockIdx.z = s selects gxc slab + out slice
// 2 CTAs/SM (107 KB SMEM, <=128 regs).
// ---------------------------------------------------------------------------
#define O_A   2560
#define ABUF  9216
#define ASTEP 18432
#define O_CS  (O_A + 2 * ASTEP)          // 39424
#define O_ST  (O_CS + 256 * 33 * 4)      // 73216
#define STP   264                        // stage pitch (halves)
#define MM_SMEM (O_ST + 64 * STP * 2)    // 107008

__global__ __launch_bounds__(256, 2) void bilstm_mma(
    const __half* __restrict__ gxh, const int* __restrict__ nbr,
    const float* __restrict__ WhhP, float* __restrict__ outP, int N, int K)
{
    extern __shared__ char smc[];
    int* ids = (int*)smc;
    const uint32_t sb = smem_u32(smc);

    const int tid = threadIdx.x;
    const int lane = tid & 31, w = tid >> 5;
    const int dir = blockIdx.y;

    float* cst = (float*)(smc + O_CS) + tid * 33;

    const __half* gx = gxh;
    const float* Whh = WhhP;
    float* out = outP;
    const int* idx = nbr;
    if (nbr) {
        int z = blockIdx.z;
        int s = z / 3, d = z - s * 3;
        gx  += (size_t)s * N * ROW;
        idx  = nbr + (size_t)(s * 3 + d) * N * K;
        Whh += (size_t)s * 2 * GATE * HH;
        out += (size_t)(d * 3 + s) * N * DD;
    } else {
        gx  += (size_t)blockIdx.z * N * K * ROW;
        out += (size_t)blockIdx.z * N * DD;
    }
    Whh += (size_t)dir * GATE * HH;
    const int node0 = blockIdx.x * 64;

    if (nbr) {
        for (int i = tid; i < 64 * K; i += 256) {
            int m = i / K;
            int n = node0 + m;
            ids[i] = (n < N) ? idx[(size_t)n * K + (i - m * K)] : 0;
        }
    }
    for (int i = tid; i < ASTEP / 4; i += 256)
        ((float*)(smc + O_A))[i] = 0.f;
#pragma unroll
    for (int i = 0; i < 32; i++) cst[i] = 0.f;

    // Persistent B fragments, gate-major permutation (split-bf16 from fp32 Whh)
    const int uw = w << 3;
    uint32_t bh[4][4][2], bl[4][4][2];
    {
        const int jr = uw + (lane >> 2);
        const int kq = (lane & 3) << 1;
#pragma unroll
        for (int g = 0; g < 4; g++) {
            const float* wr = Whh + (size_t)(g * 64 + jr) * HH;
#pragma unroll
            for (int kt = 0; kt < 4; kt++) {
#pragma unroll
                for (int hb = 0; hb < 2; hb++) {
                    float2 x = *(const float2*)(wr + kt * 16 + kq + hb * 8);
                    float lx, ly;
                    bh[g][kt][hb] = pack_hi(x.x, x.y, lx, ly);
                    bl[g][kt][hb] = pack_bf(lx, ly);
                }
            }
        }
    }
    __syncthreads();

    const int gA = lane >> 3, rA = lane & 7;
    const int arow = ((gA & 1) << 3) + rA;
    const int acol = (gA >> 1) << 4;

    const int rq = lane >> 2;
    const int u = uw + ((lane & 3) << 1);

    const __half* gdir = gx + dir * GATE;
    const __half* stg = (const __half*)(smc + O_ST);
    const int srow = tid >> 2;
    const int sch = tid & 3;

    for (int t = 0; t < K; t++) {
        const int tt = dir ? (K - 1 - t) : t;
        const uint32_t rb = sb + O_A + (uint32_t)(t & 1) * ASTEP;
        char* wbp = smc + O_A + ((t + 1) & 1) * ASTEP;

        // Stage this step's 64 gathered rows (256 halves each) into SMEM.
        {
            size_t grow;
            if (nbr) {
                grow = (size_t)ids[srow * K + tt];
            } else {
                int n = node0 + srow;
                grow = (size_t)(n < N ? n : N - 1) * K + tt;
            }
            const uint4* src = (const uint4*)(gdir + grow * ROW) + sch * 8;
            uint4* dst = (uint4*)(smc + O_ST + srow * (STP * 2)) + sch * 8;
#pragma unroll
            for (int q = 0; q < 8; q++) dst[q] = src[q];
        }
        __syncthreads();   // stage ready

#pragma unroll
        for (int mt = 0; mt < 4; mt++) {
            const int m0 = (mt << 4) + rq, m1 = m0 + 8;
            const __half* sp0 = stg + m0 * STP + u;
            const __half* sp1 = stg + m1 * STP + u;

            const uint32_t ab = rb + (uint32_t)((mt << 4) + arow) * 144 + acol;

            float fg[4][4];
#pragma unroll
            for (int g = 0; g < 4; g++) {
                float2 a0 = __half22float2(*(const __half2*)(sp0 + (g << 6)));
                float2 a1 = __half22float2(*(const __half2*)(sp1 + (g << 6)));
                fg[g][0] = a0.x; fg[g][1] = a0.y; fg[g][2] = a1.x; fg[g][3] = a1.y;
            }

            uint32_t af[4][4];
#pragma unroll
            for (int kt = 0; kt < 4; kt++) ldmx4(af[kt], ab + kt * 32);
#pragma unroll
            for (int g = 0; g < 4; g++)
#pragma unroll
                for (int kt = 0; kt < 4; kt++) {
                    mma16816(fg[g][0], fg[g][1], fg[g][2], fg[g][3], af[kt], bh[g][kt]);
                    mma16816(fg[g][0], fg[g][1], fg[g][2], fg[g][3], af[kt], bl[g][kt]);
                }

#pragma unroll
            for (int kt = 0; kt < 4; kt++) ldmx4(af[kt], ab + ABUF + kt * 32);
#pragma unroll
            for (int g = 0; g < 4; g++)
#pragma unroll
                for (int kt = 0; kt < 4; kt++)
                    mma16816(fg[g][0], fg[g][1], fg[g][2], fg[g][3], af[kt], bh[g][kt]);

            unsigned short hh[4], hl[4];
#pragma unroll
            for (int pos = 0; pos < 4; pos++) {
                float cc = cst[mt * 4 + pos];
                cc = sigm(fg[1][pos]) * cc + sigm(fg[0][pos]) * tanh_(fg[2][pos]);
                cst[mt * 4 + pos] = cc;
                float h = sigm(fg[3][pos]) * tanh_(cc);
                cst[16 + mt * 4 + pos] += h;
                __nv_bfloat16 hb16 = __float2bfloat16_rn(h);
                __nv_bfloat16 lb16 = __float2bfloat16_rn(h - __bfloat162float(hb16));
                hh[pos] = __bfloat16_as_ushort(hb16);
                hl[pos] = __bfloat16_as_ushort(lb16);
            }
            *(uint32_t*)(wbp + m0 * 144 + u * 2) =
                (uint32_t)hh[0] | ((uint32_t)hh[1] << 16);
            *(uint32_t*)(wbp + ABUF + m0 * 144 + u * 2) =
                (uint32_t)hl[0] | ((uint32_t)hl[1] << 16);
            *(uint32_t*)(wbp + m1 * 144 + u * 2) =
                (uint32_t)hh[2] | ((uint32_t)hh[3] << 16);
            *(uint32_t*)(wbp + ABUF + m1 * 144 + u * 2) =
                (uint32_t)hl[2] | ((uint32_t)hl[3] << 16);
        }
        __syncthreads();   // H writes + stage reads done before next iteration
    }

    const float inv = 1.f / (float)K;
#pragma unroll
    for (int mt = 0; mt < 4; mt++) {
        const int n0 = node0 + (mt << 4) + rq;
        const int n1 = n0 + 8;
        if (n0 < N)
            *(float2*)(out + (size_t)n0 * DD + dir * HH + u) =
                make_float2(cst[16 + mt * 4 + 0] * inv, cst[16 + mt * 4 + 1] * inv);
        if (n1 < N)
            *(float2*)(out + (size_t)n1 * DD + dir * HH + u) =
                make_float2(cst[16 + mt * 4 + 2] * inv, cst[16 + mt * 4 + 3] * inv);
    }
}

// ---------------------------------------------------------------------------
// Attention fusion: one warp per (d, n).
// ---------------------------------------------------------------------------
__global__ void attn_fuse(const float* __restrict__ content,
                          const float* __restrict__ neigh,
                          const float* __restrict__ attn_w,
                          const float* __restrict__ attn_b,
                          float* __restrict__ out, int N)
{
    int w = (blockIdx.x * blockDim.x + threadIdx.x) >> 5;
    if (w >= 3 * N) return;
    int lane = threadIdx.x & 31;
    int d = w / N, n = w - d * N;

    const float* dh = content + ((size_t)d * N + n) * DD;
    const float* aw = attn_w + d * 256;
    float4 w1 = *(const float4*)(aw + lane * 4);
    float4 w2 = *(const float4*)(aw + 128 + lane * 4);

    float4 s[4];
#pragma unroll
    for (int i = 0; i < 3; i++)
        s[i] = *(const float4*)(neigh + (((size_t)(d * 3 + i)) * N + n) * DD + lane * 4);
    s[3] = *(const float4*)(dh + lane * 4);

    float base = s[3].x * w1.x + s[3].y * w1.y + s[3].z * w1.z + s[3].w * w1.w;
    float l[4];
#pragma unroll
    for (int i = 0; i < 4; i++)
        l[i] = s[i].x * w2.x + s[i].y * w2.y + s[i].z * w2.z + s[i].w * w2.w;

#pragma unroll
    for (int off = 16; off; off >>= 1) {
        base += __shfl_xor_sync(0xffffffffu, base, off);
#pragma unroll
        for (int i = 0; i < 4; i++) l[i] += __shfl_xor_sync(0xffffffffu, l[i], off);
    }

    float b = attn_b[d];
    float mx = -1e30f;
#pragma unroll
    for (int i = 0; i < 4; i++) {
        float v = base + l[i] + b;
        l[i] = v > 0.f ? v : 0.01f * v;
        mx = fmaxf(mx, l[i]);
    }
    float se = 0.f;
#pragma unroll
    for (int i = 0; i < 4; i++) { l[i] = __expf(l[i] - mx); se += l[i]; }
    float inv = 1.f / se;

    float4 o = make_float4(0.f, 0.f, 0.f, 0.f);
#pragma unroll
    for (int i = 0; i < 4; i++) {
        float wi = l[i] * inv;
        o.x += wi * s[i].x; o.y += wi * s[i].y; o.z += wi * s[i].z; o.w += wi * s[i].w;
    }
    *(float4*)(out + ((size_t)d * N + n) * DD + lane * 4) = o;
}

// ---------------------------------------------------------------------------
extern "C" void kernel_launch(void* const* d_in, const int* in_sizes, int n_in,
                              void* d_out, int out_size)
{
    const float* xs[3]   = {(const float*)d_in[0], (const float*)d_in[1], (const float*)d_in[2]};
    const float* Wih_c   = (const float*)d_in[3];
    const float* Whh_c   = (const float*)d_in[4];
    const float* bih_c   = (const float*)d_in[5];
    const float* bhh_c   = (const float*)d_in[6];
    const float* Wih_n   = (const float*)d_in[7];
    const float* Whh_n   = (const float*)d_in[8];
    const float* bih_n   = (const float*)d_in[9];
    const float* bhh_n   = (const float*)d_in[10];
    const float* attn_w  = (const float*)d_in[11];
    const float* attn_b  = (const float*)d_in[12];
    const int*   nbr     = (const int*)d_in[13];
    float* out = (float*)d_out;

    const int N = in_sizes[0] / (3 * DD);   // 30000

    float *content, *neigh, *bsum;
    unsigned short *gxc, *gxn;
    uint32_t* bp;
    cudaGetSymbolAddress((void**)&gxc,     g_gxc);
    cudaGetSymbolAddress((void**)&gxn,     g_gxn);
    cudaGetSymbolAddress((void**)&content, g_content);
    cudaGetSymbolAddress((void**)&neigh,   g_neigh);
    cudaGetSymbolAddress((void**)&bp,      g_bp);
    cudaGetSymbolAddress((void**)&bsum,    g_bsum);

    cudaFuncSetAttribute(gemm_tc,    cudaFuncAttributeMaxDynamicSharedMemorySize, GT_SMEM);
    cudaFuncSetAttribute(bilstm_mma, cudaFuncAttributeMaxDynamicSharedMemorySize, MM_SMEM);

    const int nt = (N + 63) / 64;
    const size_t cslab = (size_t)N * 3 * ROW;   // content slab stride (halves)

    // Stage 0: pack input-projection weights into fragment-native split-bf16
    prep_weights<<<4, 256>>>(Wih_c, bih_c, bhh_c, Wih_n, bih_n, bhh_n);

    // Stage A: 3 content input projections (shared weights, set 0) into slabs
    for (int s = 0; s < 3; s++)
        gemm_tc<<<(3 * N + 63) / 64, 256, GT_SMEM>>>(
            xs[s], bp, bsum, (__half*)(gxc + s * cslab), 3 * N);

    // Stage B: all 3 content bi-LSTMs in ONE launch (grid z = s)
    bilstm_mma<<<dim3(nt, 2, 3), 256, MM_SMEM>>>(
        (const __half*)gxc, nullptr, Whh_c, content, N, 3);

    // Stage C: neighbor gate pre-activations per source type (sets 1..3)
    for (int s = 0; s < 3; s++)
        gemm_tc<<<nt, 256, GT_SMEM>>>(
            content + (size_t)s * N * DD,
            bp + (size_t)(s + 1) * 65536,
            bsum + (size_t)(s + 1) * 512,
            (__half*)(gxn + (size_t)s * N * ROW), N);

    // Stage D: 9 neighbor bi-LSTM reductions (fp16 staged gathers)
    bilstm_mma<<<dim3(nt, 2, 9), 256, MM_SMEM>>>(
        (const __half*)gxn, nbr, Whh_n, neigh, N, 10);

    // Stage E: attention fusion
    attn_fuse<<<(3 * N + 7) / 8, 256>>>(content, neigh, attn_w, attn_b, out, N);
}

// round 16
// speedup vs baseline: 1.2904x; 1.2904x over previous
#include <cuda_runtime.h>
#include <cuda_bf16.h>
#include <cuda_fp16.h>
#include <cstdint>

// Problem constants (fixed by the dataset): N=30000, C=3, D=128, K=10, H=64
#define DD   128
#define HH   64
#define GATE 256   // 4*H per direction
#define ROW  512   // gate values per row (both directions)

#define NMAX 30000

// Scratch (static device globals — allocation-free rule)
// gx pre-activations: fp16, fragment-native packed layout per row:
//   pos = dir*256 + (u>>1)*8 + g*2 + (u&1)   (512 halves = 1KB per row)
// so one lane's 4-gate init for a row is a single 16B load.
__device__ __align__(16) unsigned short g_gxc[(size_t)3 * NMAX * 3 * ROW]; // content slabs (rows n*3+t)
__device__ __align__(16) unsigned short g_gxn[(size_t)3 * NMAX * ROW];     // neighbor preacts per s
__device__ __align__(16) float g_content[(size_t)3 * NMAX * DD];           // content embeddings
__device__ __align__(16) float g_neigh[(size_t)9 * NMAX * DD];             // neigh[d][s][n][128]

// Fragment-native split-bf16 input weights + fused biases (4 sets)
__device__ __align__(16) uint32_t g_bp[4][65536];
__device__ float g_bsum[4][512];

__device__ __forceinline__ float sigm(float x) { return __fdividef(1.f, 1.f + __expf(-x)); }
__device__ __forceinline__ float tanh_(float x) { return 2.f * __fdividef(1.f, 1.f + __expf(-2.f * x)) - 1.f; }

__device__ __forceinline__ uint32_t smem_u32(const void* p) {
    uint32_t a;
    asm("{ .reg .u64 t; cvta.to.shared.u64 t, %1; cvt.u32.u64 %0, t; }" : "=r"(a) : "l"(p));
    return a;
}

// warp-level bf16 MMA  D(16x8,f32) += A(16x16,bf16 row) * B(16x8,bf16 col)
__device__ __forceinline__ void mma16816(float& f0, float& f1, float& f2, float& f3,
                                         const uint32_t* a, const uint32_t* b) {
    asm volatile(
        "mma.sync.aligned.m16n8k16.row.col.f32.bf16.bf16.f32 "
        "{%0,%1,%2,%3}, {%4,%5,%6,%7}, {%8,%9}, {%0,%1,%2,%3};"
        : "+f"(f0), "+f"(f1), "+f"(f2), "+f"(f3)
        : "r"(a[0]), "r"(a[1]), "r"(a[2]), "r"(a[3]), "r"(b[0]), "r"(b[1]));
}
__device__ __forceinline__ void ldmx4(uint32_t* r, uint32_t addr) {
    asm volatile("ldmatrix.sync.aligned.m8n8.x4.shared.b16 {%0,%1,%2,%3}, [%4];"
        : "=r"(r[0]), "=r"(r[1]), "=r"(r[2]), "=r"(r[3]) : "r"(addr));
}

__device__ __forceinline__ uint32_t pack_hi(float x, float y, float& rx, float& ry) {
    __nv_bfloat16 hx = __float2bfloat16_rn(x);
    __nv_bfloat16 hy = __float2bfloat16_rn(y);
    rx = x - __bfloat162float(hx);
    ry = y - __bfloat162float(hy);
    return ((uint32_t)__bfloat16_as_ushort(hy) << 16) | (uint32_t)__bfloat16_as_ushort(hx);
}
__device__ __forceinline__ uint32_t pack_bf(float x, float y) {
    return ((uint32_t)__bfloat16_as_ushort(__float2bfloat16_rn(y)) << 16)
         | (uint32_t)__bfloat16_as_ushort(__float2bfloat16_rn(x));
}

// ---------------------------------------------------------------------------
// Weight prep (R14): 4 input-projection sets [512][128] fp32 -> fragment-native
// split-bf16, biases fused.  blockIdx.x = set.
// ---------------------------------------------------------------------------
__global__ void prep_weights(const float* __restrict__ Wc,
                             const float* __restrict__ b1c, const float* __restrict__ b2c,
                             const float* __restrict__ Wn,
                             const float* __restrict__ b1n, const float* __restrict__ b2n)
{
    const int set = blockIdx.x;
    const float* W  = (set == 0) ? Wc : (Wn + (size_t)(set - 1) * 512 * 128);
    const float* b1 = (set == 0) ? b1c : (b1n + (size_t)(set - 1) * 512);
    const float* b2 = (set == 0) ? b2c : (b2n + (size_t)(set - 1) * 512);

    for (int i = threadIdx.x; i < 32768; i += blockDim.x) {
        int r    = i & 1;
        int nt   = (i >> 1) & 7;
        int lane = (i >> 4) & 31;
        int kt   = (i >> 9) & 7;
        int nb   = (i >> 12) & 7;
        int j = nb * 64 + nt * 8 + (lane >> 2);
        int k = kt * 16 + ((lane & 3) << 1) + r * 8;
        float w0 = W[(size_t)j * 128 + k];
        float w1 = W[(size_t)j * 128 + k + 1];
        float l0, l1;
        uint32_t hi = pack_hi(w0, w1, l0, l1);
        uint32_t lo = pack_bf(l0, l1);
        uint32_t base = (uint32_t)((nb * 8 + kt) * 32 + lane) * 32;
        g_bp[set][base + nt * 2 + r]      = hi;
        g_bp[set][base + 16 + nt * 2 + r] = lo;
    }
    for (int j = threadIdx.x; j < 512; j += blockDim.x)
        g_bsum[set][j] = b1[j] + b2[j];
}

// ---------------------------------------------------------------------------
// Tensor-core GEMM: C = A @ W^T + bsum, output fp16 in PACKED gx layout.
// Epilogue maps column j -> pos = dir*256 + (u>>1)*8 + g*2 + (u&1),
//   j = dir*256 + g*64 + u.  (cq even -> stores are __half2 at pos.)
// ---------------------------------------------------------------------------
#define APITCH 272
#define ATILE  (64 * APITCH)
#define GT_SMEM (2 * ATILE)

__global__ __launch_bounds__(256, 2) void gemm_tc(
    const float* __restrict__ A, const uint32_t* __restrict__ Bp,
    const float* __restrict__ bsum, __half* __restrict__ C, int M)
{
    extern __shared__ char smc[];
    const uint32_t sb = smem_u32(smc);
    const int tid = threadIdx.x;
    const int lane = tid & 31, w = tid >> 5;
    const int row0 = blockIdx.x * 64;

    for (int q = tid; q < 64 * 32; q += 256) {
        int r = q >> 5;
        int kc = (q & 31) << 2;
        int gm = row0 + r;
        float4 v = make_float4(0.f, 0.f, 0.f, 0.f);
        if (gm < M) v = *(const float4*)(A + (size_t)gm * 128 + kc);
        float lx, ly, lz, lw;
        uint32_t h01 = pack_hi(v.x, v.y, lx, ly);
        uint32_t h23 = pack_hi(v.z, v.w, lz, lw);
        uint32_t l01 = pack_bf(lx, ly);
        uint32_t l23 = pack_bf(lz, lw);
        char* pr = smc + r * APITCH + kc * 2;
        *(uint2*)(pr)         = make_uint2(h01, h23);
        *(uint2*)(pr + ATILE) = make_uint2(l01, l23);
    }
    __syncthreads();

    const int cq = (lane & 3) << 1;
    const int rq = lane >> 2;
    float2 bv[8];
#pragma unroll
    for (int nt = 0; nt < 8; nt++)
        bv[nt] = *(const float2*)(bsum + w * 64 + nt * 8 + cq);

    const int gA = lane >> 3, rA = lane & 7;
    const int arow = ((gA & 1) << 3) + rA;
    const int acol = (gA >> 1) << 4;
    const uint32_t abase0 = sb + (uint32_t)arow * APITCH + acol;

    const uint32_t* bpw = Bp + (uint32_t)w * (8 * 32 * 32);

    // Precompute packed positions for this thread's 8 column pairs
    int pos[8];
#pragma unroll
    for (int nt = 0; nt < 8; nt++) {
        int c0 = w * 64 + nt * 8 + cq;          // j (even)
        int dir = c0 >> 8;
        int rem = c0 & 255;
        int g = rem >> 6;
        int u = rem & 63;
        pos[nt] = (dir << 8) + ((u >> 1) << 3) + (g << 1);
    }

#pragma unroll
    for (int mt = 0; mt < 4; mt++) {
        float acc[8][4];
#pragma unroll
        for (int nt = 0; nt < 8; nt++) {
            acc[nt][0] = bv[nt].x; acc[nt][1] = bv[nt].y;
            acc[nt][2] = bv[nt].x; acc[nt][3] = bv[nt].y;
        }

#pragma unroll
        for (int kt = 0; kt < 8; kt++) {
            uint32_t bfr[32];
            const uint32_t* bp = bpw + (uint32_t)(kt * 32 + lane) * 32;
#pragma unroll
            for (int q = 0; q < 8; q++)
                *(uint4*)&bfr[q * 4] = *(const uint4*)(bp + q * 4);

            const uint32_t ab = abase0 + (uint32_t)(mt * 16) * APITCH + kt * 32;
            uint32_t af[4];
            ldmx4(af, ab);
#pragma unroll
            for (int nt = 0; nt < 8; nt++) {
                mma16816(acc[nt][0], acc[nt][1], acc[nt][2], acc[nt][3], af, &bfr[nt * 2]);
                mma16816(acc[nt][0], acc[nt][1], acc[nt][2], acc[nt][3], af, &bfr[16 + nt * 2]);
            }
            ldmx4(af, ab + ATILE);
#pragma unroll
            for (int nt = 0; nt < 8; nt++)
                mma16816(acc[nt][0], acc[nt][1], acc[nt][2], acc[nt][3], af, &bfr[nt * 2]);
        }

        const int m0 = row0 + mt * 16 + rq;
        const int m1 = m0 + 8;
#pragma unroll
        for (int nt = 0; nt < 8; nt++) {
            if (m0 < M)
                *(__half2*)(C + (size_t)m0 * ROW + pos[nt]) = __floats2half2_rn(acc[nt][0], acc[nt][1]);
            if (m1 < M)
                *(__half2*)(C + (size_t)m1 * ROW + pos[nt]) = __floats2half2_rn(acc[nt][2], acc[nt][3]);
        }
    }
}

// ---------------------------------------------------------------------------
// Bi-LSTM recurrence on warp MMAs (split-bf16 hi/lo, fp32 accum), v5:
//   R14 structure (direct per-lane gathers, one barrier/step, 2 CTAs/SM)
//   but gx is fp16 PACKED: one LDG.128 per (row, thread) fetches all 4 gates.
//   content mode (nbr==null): blockIdx.z = s selects gxc slab + out slice.
// ---------------------------------------------------------------------------
#define O_A   2560
#define ABUF  9216
#define ASTEP 18432
#define O_CS  (O_A + 2 * ASTEP)          // 39424
#define MM_SMEM (O_CS + 256 * 33 * 4)    // 73216

__global__ __launch_bounds__(256, 2) void bilstm_mma(
    const __half* __restrict__ gxh, const int* __restrict__ nbr,
    const float* __restrict__ WhhP, float* __restrict__ outP, int N, int K)
{
    extern __shared__ char smc[];
    int* ids = (int*)smc;
    const uint32_t sb = smem_u32(smc);

    const int tid = threadIdx.x;
    const int lane = tid & 31, w = tid >> 5;
    const int dir = blockIdx.y;

    float* cst = (float*)(smc + O_CS) + tid * 33;

    const __half* gx = gxh;
    const float* Whh = WhhP;
    float* out = outP;
    const int* idx = nbr;
    if (nbr) {
        int z = blockIdx.z;
        int s = z / 3, d = z - s * 3;
        gx  += (size_t)s * N * ROW;
        idx  = nbr + (size_t)(s * 3 + d) * N * K;
        Whh += (size_t)s * 2 * GATE * HH;
        out += (size_t)(d * 3 + s) * N * DD;
    } else {
        gx  += (size_t)blockIdx.z * N * K * ROW;
        out += (size_t)blockIdx.z * N * DD;
    }
    Whh += (size_t)dir * GATE * HH;
    const int node0 = blockIdx.x * 64;

    if (nbr) {
        for (int i = tid; i < 64 * K; i += 256) {
            int m = i / K;
            int n = node0 + m;
            ids[i] = (n < N) ? idx[(size_t)n * K + (i - m * K)] : 0;
        }
    }
    for (int i = tid; i < ASTEP / 4; i += 256)
        ((float*)(smc + O_A))[i] = 0.f;
#pragma unroll
    for (int i = 0; i < 32; i++) cst[i] = 0.f;

    // Persistent B fragments, gate-major permutation (split-bf16 from fp32 Whh)
    const int uw = w << 3;
    uint32_t bh[4][4][2], bl[4][4][2];
    {
        const int jr = uw + (lane >> 2);
        const int kq = (lane & 3) << 1;
#pragma unroll
        for (int g = 0; g < 4; g++) {
            const float* wr = Whh + (size_t)(g * 64 + jr) * HH;
#pragma unroll
            for (int kt = 0; kt < 4; kt++) {
#pragma unroll
                for (int hb = 0; hb < 2; hb++) {
                    float2 x = *(const float2*)(wr + kt * 16 + kq + hb * 8);
                    float lx, ly;
                    bh[g][kt][hb] = pack_hi(x.x, x.y, lx, ly);
                    bl[g][kt][hb] = pack_bf(lx, ly);
                }
            }
        }
    }
    __syncthreads();

    const int gA = lane >> 3, rA = lane & 7;
    const int arow = ((gA & 1) << 3) + rA;
    const int acol = (gA >> 1) << 4;

    const int rq = lane >> 2;
    const int u = uw + ((lane & 3) << 1);

    // Packed-chunk offset for this thread: dir*256 + (u>>1)*8 halves
    const int choff = (dir << 8) + ((u >> 1) << 3);

    for (int t = 0; t < K; t++) {
        const int tt = dir ? (K - 1 - t) : t;
        const uint32_t rb = sb + O_A + (uint32_t)(t & 1) * ASTEP;
        char* wbp = smc + O_A + ((t + 1) & 1) * ASTEP;

#pragma unroll
        for (int mt = 0; mt < 4; mt++) {
            const int m0 = (mt << 4) + rq, m1 = m0 + 8;
            size_t row0, row1;
            if (nbr) {
                row0 = (size_t)ids[m0 * K + tt];
                row1 = (size_t)ids[m1 * K + tt];
            } else {
                int n0 = node0 + m0, n1 = node0 + m1;
                row0 = (size_t)(n0 < N ? n0 : N - 1) * K + tt;
                row1 = (size_t)(n1 < N ? n1 : N - 1) * K + tt;
            }

            // One 16B load per row: all 4 gates for this thread's u-pair
            uint4 cp0 = *(const uint4*)(gx + row0 * ROW + choff);
            uint4 cp1 = *(const uint4*)(gx + row1 * ROW + choff);

            const uint32_t ab = rb + (uint32_t)((mt << 4) + arow) * 144 + acol;

            float fg[4][4];
            {
                const __half2* h0 = (const __half2*)&cp0;
                const __half2* h1 = (const __half2*)&cp1;
#pragma unroll
                for (int g = 0; g < 4; g++) {
                    float2 a0 = __half22float2(h0[g]);
                    float2 a1 = __half22float2(h1[g]);
                    fg[g][0] = a0.x; fg[g][1] = a0.y; fg[g][2] = a1.x; fg[g][3] = a1.y;
                }
            }

            uint32_t af[4][4];
#pragma unroll
            for (int kt = 0; kt < 4; kt++) ldmx4(af[kt], ab + kt * 32);
#pragma unroll
            for (int g = 0; g < 4; g++)
#pragma unroll
                for (int kt = 0; kt < 4; kt++) {
                    mma16816(fg[g][0], fg[g][1], fg[g][2], fg[g][3], af[kt], bh[g][kt]);
                    mma16816(fg[g][0], fg[g][1], fg[g][2], fg[g][3], af[kt], bl[g][kt]);
                }

#pragma unroll
            for (int kt = 0; kt < 4; kt++) ldmx4(af[kt], ab + ABUF + kt * 32);
#pragma unroll
            for (int g = 0; g < 4; g++)
#pragma unroll
                for (int kt = 0; kt < 4; kt++)
                    mma16816(fg[g][0], fg[g][1], fg[g][2], fg[g][3], af[kt], bh[g][kt]);

            unsigned short hh[4], hl[4];
#pragma unroll
            for (int pos = 0; pos < 4; pos++) {
                float cc = cst[mt * 4 + pos];
                cc = sigm(fg[1][pos]) * cc + sigm(fg[0][pos]) * tanh_(fg[2][pos]);
                cst[mt * 4 + pos] = cc;
                float h = sigm(fg[3][pos]) * tanh_(cc);
                cst[16 + mt * 4 + pos] += h;
                __nv_bfloat16 hb16 = __float2bfloat16_rn(h);
                __nv_bfloat16 lb16 = __float2bfloat16_rn(h - __bfloat162float(hb16));
                hh[pos] = __bfloat16_as_ushort(hb16);
                hl[pos] = __bfloat16_as_ushort(lb16);
            }
            *(uint32_t*)(wbp + m0 * 144 + u * 2) =
                (uint32_t)hh[0] | ((uint32_t)hh[1] << 16);
            *(uint32_t*)(wbp + ABUF + m0 * 144 + u * 2) =
                (uint32_t)hl[0] | ((uint32_t)hl[1] << 16);
            *(uint32_t*)(wbp + m1 * 144 + u * 2) =
                (uint32_t)hh[2] | ((uint32_t)hh[3] << 16);
            *(uint32_t*)(wbp + ABUF + m1 * 144 + u * 2) =
                (uint32_t)hl[2] | ((uint32_t)hl[3] << 16);
        }
        __syncthreads();
    }

    const float inv = 1.f / (float)K;
#pragma unroll
    for (int mt = 0; mt < 4; mt++) {
        const int n0 = node0 + (mt << 4) + rq;
        const int n1 = n0 + 8;
        if (n0 < N)
            *(float2*)(out + (size_t)n0 * DD + dir * HH + u) =
                make_float2(cst[16 + mt * 4 + 0] * inv, cst[16 + mt * 4 + 1] * inv);
        if (n1 < N)
            *(float2*)(out + (size_t)n1 * DD + dir * HH + u) =
                make_float2(cst[16 + mt * 4 + 2] * inv, cst[16 + mt * 4 + 3] * inv);
    }
}

// ---------------------------------------------------------------------------
// Attention fusion: one warp per (d, n).
// ---------------------------------------------------------------------------
__global__ void attn_fuse(const float* __restrict__ content,
                          const float* __restrict__ neigh,
                          const float* __restrict__ attn_w,
                          const float* __restrict__ attn_b,
                          float* __restrict__ out, int N)
{
    int w = (blockIdx.x * blockDim.x + threadIdx.x) >> 5;
    if (w >= 3 * N) return;
    int lane = threadIdx.x & 31;
    int d = w / N, n = w - d * N;

    const float* dh = content + ((size_t)d * N + n) * DD;
    const float* aw = attn_w + d * 256;
    float4 w1 = *(const float4*)(aw + lane * 4);
    float4 w2 = *(const float4*)(aw + 128 + lane * 4);

    float4 s[4];
#pragma unroll
    for (int i = 0; i < 3; i++)
        s[i] = *(const float4*)(neigh + (((size_t)(d * 3 + i)) * N + n) * DD + lane * 4);
    s[3] = *(const float4*)(dh + lane * 4);

    float base = s[3].x * w1.x + s[3].y * w1.y + s[3].z * w1.z + s[3].w * w1.w;
    float l[4];
#pragma unroll
    for (int i = 0; i < 4; i++)
        l[i] = s[i].x * w2.x + s[i].y * w2.y + s[i].z * w2.z + s[i].w * w2.w;

#pragma unroll
    for (int off = 16; off; off >>= 1) {
        base += __shfl_xor_sync(0xffffffffu, base, off);
#pragma unroll
        for (int i = 0; i < 4; i++) l[i] += __shfl_xor_sync(0xffffffffu, l[i], off);
    }

    float b = attn_b[d];
    float mx = -1e30f;
#pragma unroll
    for (int i = 0; i < 4; i++) {
        float v = base + l[i] + b;
        l[i] = v > 0.f ? v : 0.01f * v;
        mx = fmaxf(mx, l[i]);
    }
    float se = 0.f;
#pragma unroll
    for (int i = 0; i < 4; i++) { l[i] = __expf(l[i] - mx); se += l[i]; }
    float inv = 1.f / se;

    float4 o = make_float4(0.f, 0.f, 0.f, 0.f);
#pragma unroll
    for (int i = 0; i < 4; i++) {
        float wi = l[i] * inv;
        o.x += wi * s[i].x; o.y += wi * s[i].y; o.z += wi * s[i].z; o.w += wi * s[i].w;
    }
    *(float4*)(out + ((size_t)d * N + n) * DD + lane * 4) = o;
}

// ---------------------------------------------------------------------------
extern "C" void kernel_launch(void* const* d_in, const int* in_sizes, int n_in,
                              void* d_out, int out_size)
{
    const float* xs[3]   = {(const float*)d_in[0], (const float*)d_in[1], (const float*)d_in[2]};
    const float* Wih_c   = (const float*)d_in[3];
    const float* Whh_c   = (const float*)d_in[4];
    const float* bih_c   = (const float*)d_in[5];
    const float* bhh_c   = (const float*)d_in[6];
    const float* Wih_n   = (const float*)d_in[7];
    const float* Whh_n   = (const float*)d_in[8];
    const float* bih_n   = (const float*)d_in[9];
    const float* bhh_n   = (const float*)d_in[10];
    const float* attn_w  = (const float*)d_in[11];
    const float* attn_b  = (const float*)d_in[12];
    const int*   nbr     = (const int*)d_in[13];
    float* out = (float*)d_out;

    const int N = in_sizes[0] / (3 * DD);   // 30000

    float *content, *neigh, *bsum;
    unsigned short *gxc, *gxn;
    uint32_t* bp;
    cudaGetSymbolAddress((void**)&gxc,     g_gxc);
    cudaGetSymbolAddress((void**)&gxn,     g_gxn);
    cudaGetSymbolAddress((void**)&content, g_content);
    cudaGetSymbolAddress((void**)&neigh,   g_neigh);
    cudaGetSymbolAddress((void**)&bp,      g_bp);
    cudaGetSymbolAddress((void**)&bsum,    g_bsum);

    cudaFuncSetAttribute(gemm_tc,    cudaFuncAttributeMaxDynamicSharedMemorySize, GT_SMEM);
    cudaFuncSetAttribute(bilstm_mma, cudaFuncAttributeMaxDynamicSharedMemorySize, MM_SMEM);

    const int nt = (N + 63) / 64;
    const size_t cslab = (size_t)N * 3 * ROW;   // content slab stride (halves)

    // Stage 0: pack input-projection weights into fragment-native split-bf16
    prep_weights<<<4, 256>>>(Wih_c, bih_c, bhh_c, Wih_n, bih_n, bhh_n);

    // Stage A: 3 content input projections (shared weights, set 0) into slabs
    for (int s = 0; s < 3; s++)
        gemm_tc<<<(3 * N + 63) / 64, 256, GT_SMEM>>>(
            xs[s], bp, bsum, (__half*)(gxc + s * cslab), 3 * N);

    // Stage B: all 3 content bi-LSTMs in ONE launch (grid z = s)
    bilstm_mma<<<dim3(nt, 2, 3), 256, MM_SMEM>>>(
        (const __half*)gxc, nullptr, Whh_c, content, N, 3);

    // Stage C: neighbor gate pre-activations per source type (sets 1..3)
    for (int s = 0; s < 3; s++)
        gemm_tc<<<nt, 256, GT_SMEM>>>(
            content + (size_t)s * N * DD,
            bp + (size_t)(s + 1) * 65536,
            bsum + (size_t)(s + 1) * 512,
            (__half*)(gxn + (size_t)s * N * ROW), N);

    // Stage D: 9 neighbor bi-LSTM reductions (fp16 packed gathers)
    bilstm_mma<<<dim3(nt, 2, 9), 256, MM_SMEM>>>(
        (const __half*)gxn, nbr, Whh_n, neigh, N, 10);

    // Stage E: attention fusion
    attn_fuse<<<(3 * N + 7) / 8, 256>>>(content, neigh, attn_w, attn_b, out, N);
}

// round 17
// speedup vs baseline: 1.5031x; 1.1649x over previous
#include <cuda_runtime.h>
#include <cuda_bf16.h>
#include <cuda_fp16.h>
#include <cstdint>

// Problem constants (fixed by the dataset): N=30000, C=3, D=128, K=10, H=64
#define DD   128
#define HH   64
#define GATE 256   // 4*H per direction
#define ROW  512   // gate values per row (both directions)

#define NMAX 30000

// Scratch (static device globals — allocation-free rule)
// gx pre-activations: fp16, fragment-native packed layout per row:
//   pos = dir*256 + (u>>1)*8 + g*2 + (u&1)   (512 halves = 1KB per row)
__device__ __align__(16) unsigned short g_gxc[(size_t)3 * NMAX * 3 * ROW]; // content slabs (rows n*3+t)
__device__ __align__(16) unsigned short g_gxn[(size_t)3 * NMAX * ROW];     // neighbor preacts per s
__device__ __align__(16) float g_content[(size_t)3 * NMAX * DD];           // content embeddings
__device__ __align__(16) float g_neigh[(size_t)9 * NMAX * DD];             // neigh[d][s][n][128]

// Fragment-native split-bf16 input weights + fused biases (4 sets)
__device__ __align__(16) uint32_t g_bp[4][65536];
__device__ float g_bsum[4][512];

__device__ __forceinline__ float sigm(float x) { return __fdividef(1.f, 1.f + __expf(-x)); }
__device__ __forceinline__ float tanh_(float x) { return 2.f * __fdividef(1.f, 1.f + __expf(-2.f * x)) - 1.f; }

__device__ __forceinline__ uint32_t smem_u32(const void* p) {
    uint32_t a;
    asm("{ .reg .u64 t; cvta.to.shared.u64 t, %1; cvt.u32.u64 %0, t; }" : "=r"(a) : "l"(p));
    return a;
}

// warp-level bf16 MMA  D(16x8,f32) += A(16x16,bf16 row) * B(16x8,bf16 col)
__device__ __forceinline__ void mma16816(float& f0, float& f1, float& f2, float& f3,
                                         const uint32_t* a, const uint32_t* b) {
    asm volatile(
        "mma.sync.aligned.m16n8k16.row.col.f32.bf16.bf16.f32 "
        "{%0,%1,%2,%3}, {%4,%5,%6,%7}, {%8,%9}, {%0,%1,%2,%3};"
        : "+f"(f0), "+f"(f1), "+f"(f2), "+f"(f3)
        : "r"(a[0]), "r"(a[1]), "r"(a[2]), "r"(a[3]), "r"(b[0]), "r"(b[1]));
}
__device__ __forceinline__ void ldmx4(uint32_t* r, uint32_t addr) {
    asm volatile("ldmatrix.sync.aligned.m8n8.x4.shared.b16 {%0,%1,%2,%3}, [%4];"
        : "=r"(r[0]), "=r"(r[1]), "=r"(r[2]), "=r"(r[3]) : "r"(addr));
}

__device__ __forceinline__ uint32_t pack_hi(float x, float y, float& rx, float& ry) {
    __nv_bfloat16 hx = __float2bfloat16_rn(x);
    __nv_bfloat16 hy = __float2bfloat16_rn(y);
    rx = x - __bfloat162float(hx);
    ry = y - __bfloat162float(hy);
    return ((uint32_t)__bfloat16_as_ushort(hy) << 16) | (uint32_t)__bfloat16_as_ushort(hx);
}
__device__ __forceinline__ uint32_t pack_bf(float x, float y) {
    return ((uint32_t)__bfloat16_as_ushort(__float2bfloat16_rn(y)) << 16)
         | (uint32_t)__bfloat16_as_ushort(__float2bfloat16_rn(x));
}

// ---------------------------------------------------------------------------
// Weight prep (R14): 4 input-projection sets [512][128] fp32 -> fragment-native
// split-bf16, biases fused.  blockIdx.x = set.
// ---------------------------------------------------------------------------
__global__ void prep_weights(const float* __restrict__ Wc,
                             const float* __restrict__ b1c, const float* __restrict__ b2c,
                             const float* __restrict__ Wn,
                             const float* __restrict__ b1n, const float* __restrict__ b2n)
{
    const int set = blockIdx.x;
    const float* W  = (set == 0) ? Wc : (Wn + (size_t)(set - 1) * 512 * 128);
    const float* b1 = (set == 0) ? b1c : (b1n + (size_t)(set - 1) * 512);
    const float* b2 = (set == 0) ? b2c : (b2n + (size_t)(set - 1) * 512);

    for (int i = threadIdx.x; i < 32768; i += blockDim.x) {
        int r    = i & 1;
        int nt   = (i >> 1) & 7;
        int lane = (i >> 4) & 31;
        int kt   = (i >> 9) & 7;
        int nb   = (i >> 12) & 7;
        int j = nb * 64 + nt * 8 + (lane >> 2);
        int k = kt * 16 + ((lane & 3) << 1) + r * 8;
        float w0 = W[(size_t)j * 128 + k];
        float w1 = W[(size_t)j * 128 + k + 1];
        float l0, l1;
        uint32_t hi = pack_hi(w0, w1, l0, l1);
        uint32_t lo = pack_bf(l0, l1);
        uint32_t base = (uint32_t)((nb * 8 + kt) * 32 + lane) * 32;
        g_bp[set][base + nt * 2 + r]      = hi;
        g_bp[set][base + 16 + nt * 2 + r] = lo;
    }
    for (int j = threadIdx.x; j < 512; j += blockDim.x)
        g_bsum[set][j] = b1[j] + b2[j];
}

// ---------------------------------------------------------------------------
// Tensor-core GEMM v2: C = A @ W^T + bsum, fp16 packed-gx output.
// 512 threads; warp wn (0..15) owns 32 cols (4 nt blocks). kt is the OUTER
// loop so each B fetch (4 LDG.128/lane) serves all 4 m-tiles: per-lane B
// traffic drops 8x vs v1. Accumulators for all 4 mt live (64 regs).
// ---------------------------------------------------------------------------
#define APITCH 272
#define ATILE  (64 * APITCH)
#define GT_SMEM (2 * ATILE)

__global__ __launch_bounds__(512, 1) void gemm_tc(
    const float* __restrict__ A, const uint32_t* __restrict__ Bp,
    const float* __restrict__ bsum, __half* __restrict__ C, int M)
{
    extern __shared__ char smc[];
    const uint32_t sb = smem_u32(smc);
    const int tid = threadIdx.x;
    const int lane = tid & 31, wn = tid >> 5;
    const int row0 = blockIdx.x * 64;

    // Load A rows, convert to split-bf16 hi/lo tiles (64 rows x 128 k)
    for (int q = tid; q < 64 * 32; q += 512) {
        int r = q >> 5;
        int kc = (q & 31) << 2;
        int gm = row0 + r;
        float4 v = make_float4(0.f, 0.f, 0.f, 0.f);
        if (gm < M) v = *(const float4*)(A + (size_t)gm * 128 + kc);
        float lx, ly, lz, lw;
        uint32_t h01 = pack_hi(v.x, v.y, lx, ly);
        uint32_t h23 = pack_hi(v.z, v.w, lz, lw);
        uint32_t l01 = pack_bf(lx, ly);
        uint32_t l23 = pack_bf(lz, lw);
        char* pr = smc + r * APITCH + kc * 2;
        *(uint2*)(pr)         = make_uint2(h01, h23);
        *(uint2*)(pr + ATILE) = make_uint2(l01, l23);
    }
    __syncthreads();

    const int cq = (lane & 3) << 1;
    const int rq = lane >> 2;
    const int nb = wn >> 1;            // 64-col band in packed B
    const int half = wn & 1;           // which 4-nt half of the band

    // Bias registers for this warp's 4 nt blocks
    float2 bv[4];
#pragma unroll
    for (int nt = 0; nt < 4; nt++)
        bv[nt] = *(const float2*)(bsum + nb * 64 + (half * 4 + nt) * 8 + cq);

    // Packed positions for this thread's 4 column pairs
    int pos[4];
#pragma unroll
    for (int nt = 0; nt < 4; nt++) {
        int c0 = nb * 64 + (half * 4 + nt) * 8 + cq;   // j (even)
        int dir = c0 >> 8;
        int rem = c0 & 255;
        int g = rem >> 6;
        int u = rem & 63;
        pos[nt] = (dir << 8) + ((u >> 1) << 3) + (g << 1);
    }

    // ldmatrix lane addressing (validated mapping, pitch 272)
    const int gA = lane >> 3, rA = lane & 7;
    const int arow = ((gA & 1) << 3) + rA;
    const int acol = (gA >> 1) << 4;
    const uint32_t abase0 = sb + (uint32_t)arow * APITCH + acol;

    const uint32_t* bpw = Bp + (uint32_t)nb * (8 * 32 * 32);

    // Accumulators for all 4 m-tiles, bias-initialized
    float acc[4][4][4];   // [mt][nt][4]
#pragma unroll
    for (int mt = 0; mt < 4; mt++)
#pragma unroll
        for (int nt = 0; nt < 4; nt++) {
            acc[mt][nt][0] = bv[nt].x; acc[mt][nt][1] = bv[nt].y;
            acc[mt][nt][2] = bv[nt].x; acc[mt][nt][3] = bv[nt].y;
        }

#pragma unroll
    for (int kt = 0; kt < 8; kt++) {
        // One B fetch per kt: this half's 4 nt blocks (hi + lo), 4 LDG.128
        uint32_t bh[8], bl[8];
        {
            const uint32_t* bp = bpw + (uint32_t)(kt * 32 + lane) * 32 + half * 8;
            *(uint4*)&bh[0] = *(const uint4*)(bp);
            *(uint4*)&bh[4] = *(const uint4*)(bp + 4);
            *(uint4*)&bl[0] = *(const uint4*)(bp + 16);
            *(uint4*)&bl[4] = *(const uint4*)(bp + 20);
        }

#pragma unroll
        for (int mt = 0; mt < 4; mt++) {
            const uint32_t ab = abase0 + (uint32_t)(mt * 16) * APITCH + kt * 32;
            uint32_t af[4];
            ldmx4(af, ab);                       // A hi
#pragma unroll
            for (int nt = 0; nt < 4; nt++) {
                mma16816(acc[mt][nt][0], acc[mt][nt][1], acc[mt][nt][2], acc[mt][nt][3],
                         af, &bh[nt * 2]);
                mma16816(acc[mt][nt][0], acc[mt][nt][1], acc[mt][nt][2], acc[mt][nt][3],
                         af, &bl[nt * 2]);
            }
            ldmx4(af, ab + ATILE);               // A lo
#pragma unroll
            for (int nt = 0; nt < 4; nt++)
                mma16816(acc[mt][nt][0], acc[mt][nt][1], acc[mt][nt][2], acc[mt][nt][3],
                         af, &bh[nt * 2]);
        }
    }

    // Epilogue: fp16 packed-layout stores
#pragma unroll
    for (int mt = 0; mt < 4; mt++) {
        const int m0 = row0 + mt * 16 + rq;
        const int m1 = m0 + 8;
#pragma unroll
        for (int nt = 0; nt < 4; nt++) {
            if (m0 < M)
                *(__half2*)(C + (size_t)m0 * ROW + pos[nt]) =
                    __floats2half2_rn(acc[mt][nt][0], acc[mt][nt][1]);
            if (m1 < M)
                *(__half2*)(C + (size_t)m1 * ROW + pos[nt]) =
                    __floats2half2_rn(acc[mt][nt][2], acc[mt][nt][3]);
        }
    }
}

// ---------------------------------------------------------------------------
// Bi-LSTM recurrence on warp MMAs (split-bf16 hi/lo, fp32 accum), v5 (R16):
//   direct per-lane gathers from fp16 PACKED gx (one LDG.128 per row/thread),
//   one barrier/step, 2 CTAs/SM.
// ---------------------------------------------------------------------------
#define O_A   2560
#define ABUF  9216
#define ASTEP 18432
#define O_CS  (O_A + 2 * ASTEP)          // 39424
#define MM_SMEM (O_CS + 256 * 33 * 4)    // 73216

__global__ __launch_bounds__(256, 2) void bilstm_mma(
    const __half* __restrict__ gxh, const int* __restrict__ nbr,
    const float* __restrict__ WhhP, float* __restrict__ outP, int N, int K)
{
    extern __shared__ char smc[];
    int* ids = (int*)smc;
    const uint32_t sb = smem_u32(smc);

    const int tid = threadIdx.x;
    const int lane = tid & 31, w = tid >> 5;
    const int dir = blockIdx.y;

    float* cst = (float*)(smc + O_CS) + tid * 33;

    const __half* gx = gxh;
    const float* Whh = WhhP;
    float* out = outP;
    const int* idx = nbr;
    if (nbr) {
        int z = blockIdx.z;
        int s = z / 3, d = z - s * 3;
        gx  += (size_t)s * N * ROW;
        idx  = nbr + (size_t)(s * 3 + d) * N * K;
        Whh += (size_t)s * 2 * GATE * HH;
        out += (size_t)(d * 3 + s) * N * DD;
    } else {
        gx  += (size_t)blockIdx.z * N * K * ROW;
        out += (size_t)blockIdx.z * N * DD;
    }
    Whh += (size_t)dir * GATE * HH;
    const int node0 = blockIdx.x * 64;

    if (nbr) {
        for (int i = tid; i < 64 * K; i += 256) {
            int m = i / K;
            int n = node0 + m;
            ids[i] = (n < N) ? idx[(size_t)n * K + (i - m * K)] : 0;
        }
    }
    for (int i = tid; i < ASTEP / 4; i += 256)
        ((float*)(smc + O_A))[i] = 0.f;
#pragma unroll
    for (int i = 0; i < 32; i++) cst[i] = 0.f;

    // Persistent B fragments, gate-major permutation (split-bf16 from fp32 Whh)
    const int uw = w << 3;
    uint32_t bh[4][4][2], bl[4][4][2];
    {
        const int jr = uw + (lane >> 2);
        const int kq = (lane & 3) << 1;
#pragma unroll
        for (int g = 0; g < 4; g++) {
            const float* wr = Whh + (size_t)(g * 64 + jr) * HH;
#pragma unroll
            for (int kt = 0; kt < 4; kt++) {
#pragma unroll
                for (int hb = 0; hb < 2; hb++) {
                    float2 x = *(const float2*)(wr + kt * 16 + kq + hb * 8);
                    float lx, ly;
                    bh[g][kt][hb] = pack_hi(x.x, x.y, lx, ly);
                    bl[g][kt][hb] = pack_bf(lx, ly);
                }
            }
        }
    }
    __syncthreads();

    const int gA = lane >> 3, rA = lane & 7;
    const int arow = ((gA & 1) << 3) + rA;
    const int acol = (gA >> 1) << 4;

    const int rq = lane >> 2;
    const int u = uw + ((lane & 3) << 1);

    // Packed-chunk offset for this thread: dir*256 + (u>>1)*8 halves
    const int choff = (dir << 8) + ((u >> 1) << 3);

    for (int t = 0; t < K; t++) {
        const int tt = dir ? (K - 1 - t) : t;
        const uint32_t rb = sb + O_A + (uint32_t)(t & 1) * ASTEP;
        char* wbp = smc + O_A + ((t + 1) & 1) * ASTEP;

#pragma unroll
        for (int mt = 0; mt < 4; mt++) {
            const int m0 = (mt << 4) + rq, m1 = m0 + 8;
            size_t row0, row1;
            if (nbr) {
                row0 = (size_t)ids[m0 * K + tt];
                row1 = (size_t)ids[m1 * K + tt];
            } else {
                int n0 = node0 + m0, n1 = node0 + m1;
                row0 = (size_t)(n0 < N ? n0 : N - 1) * K + tt;
                row1 = (size_t)(n1 < N ? n1 : N - 1) * K + tt;
            }

            // One 16B load per row: all 4 gates for this thread's u-pair
            uint4 cp0 = *(const uint4*)(gx + row0 * ROW + choff);
            uint4 cp1 = *(const uint4*)(gx + row1 * ROW + choff);

            const uint32_t ab = rb + (uint32_t)((mt << 4) + arow) * 144 + acol;

            float fg[4][4];
            {
                const __half2* h0 = (const __half2*)&cp0;
                const __half2* h1 = (const __half2*)&cp1;
#pragma unroll
                for (int g = 0; g < 4; g++) {
                    float2 a0 = __half22float2(h0[g]);
                    float2 a1 = __half22float2(h1[g]);
                    fg[g][0] = a0.x; fg[g][1] = a0.y; fg[g][2] = a1.x; fg[g][3] = a1.y;
                }
            }

            uint32_t af[4][4];
#pragma unroll
            for (int kt = 0; kt < 4; kt++) ldmx4(af[kt], ab + kt * 32);
#pragma unroll
            for (int g = 0; g < 4; g++)
#pragma unroll
                for (int kt = 0; kt < 4; kt++) {
                    mma16816(fg[g][0], fg[g][1], fg[g][2], fg[g][3], af[kt], bh[g][kt]);
                    mma16816(fg[g][0], fg[g][1], fg[g][2], fg[g][3], af[kt], bl[g][kt]);
                }

#pragma unroll
            for (int kt = 0; kt < 4; kt++) ldmx4(af[kt], ab + ABUF + kt * 32);
#pragma unroll
            for (int g = 0; g < 4; g++)
#pragma unroll
                for (int kt = 0; kt < 4; kt++)
                    mma16816(fg[g][0], fg[g][1], fg[g][2], fg[g][3], af[kt], bh[g][kt]);

            unsigned short hh[4], hl[4];
#pragma unroll
            for (int pos = 0; pos < 4; pos++) {
                float cc = cst[mt * 4 + pos];
                cc = sigm(fg[1][pos]) * cc + sigm(fg[0][pos]) * tanh_(fg[2][pos]);
                cst[mt * 4 + pos] = cc;
                float h = sigm(fg[3][pos]) * tanh_(cc);
                cst[16 + mt * 4 + pos] += h;
                __nv_bfloat16 hb16 = __float2bfloat16_rn(h);
                __nv_bfloat16 lb16 = __float2bfloat16_rn(h - __bfloat162float(hb16));
                hh[pos] = __bfloat16_as_ushort(hb16);
                hl[pos] = __bfloat16_as_ushort(lb16);
            }
            *(uint32_t*)(wbp + m0 * 144 + u * 2) =
                (uint32_t)hh[0] | ((uint32_t)hh[1] << 16);
            *(uint32_t*)(wbp + ABUF + m0 * 144 + u * 2) =
                (uint32_t)hl[0] | ((uint32_t)hl[1] << 16);
            *(uint32_t*)(wbp + m1 * 144 + u * 2) =
                (uint32_t)hh[2] | ((uint32_t)hh[3] << 16);
            *(uint32_t*)(wbp + ABUF + m1 * 144 + u * 2) =
                (uint32_t)hl[2] | ((uint32_t)hl[3] << 16);
        }
        __syncthreads();
    }

    const float inv = 1.f / (float)K;
#pragma unroll
    for (int mt = 0; mt < 4; mt++) {
        const int n0 = node0 + (mt << 4) + rq;
        const int n1 = n0 + 8;
        if (n0 < N)
            *(float2*)(out + (size_t)n0 * DD + dir * HH + u) =
                make_float2(cst[16 + mt * 4 + 0] * inv, cst[16 + mt * 4 + 1] * inv);
        if (n1 < N)
            *(float2*)(out + (size_t)n1 * DD + dir * HH + u) =
                make_float2(cst[16 + mt * 4 + 2] * inv, cst[16 + mt * 4 + 3] * inv);
    }
}

// ---------------------------------------------------------------------------
// Attention fusion: one warp per (d, n).
// ---------------------------------------------------------------------------
__global__ void attn_fuse(const float* __restrict__ content,
                          const float* __restrict__ neigh,
                          const float* __restrict__ attn_w,
                          const float* __restrict__ attn_b,
                          float* __restrict__ out, int N)
{
    int w = (blockIdx.x * blockDim.x + threadIdx.x) >> 5;
    if (w >= 3 * N) return;
    int lane = threadIdx.x & 31;
    int d = w / N, n = w - d * N;

    const float* dh = content + ((size_t)d * N + n) * DD;
    const float* aw = attn_w + d * 256;
    float4 w1 = *(const float4*)(aw + lane * 4);
    float4 w2 = *(const float4*)(aw + 128 + lane * 4);

    float4 s[4];
#pragma unroll
    for (int i = 0; i < 3; i++)
        s[i] = *(const float4*)(neigh + (((size_t)(d * 3 + i)) * N + n) * DD + lane * 4);
    s[3] = *(const float4*)(dh + lane * 4);

    float base = s[3].x * w1.x + s[3].y * w1.y + s[3].z * w1.z + s[3].w * w1.w;
    float l[4];
#pragma unroll
    for (int i = 0; i < 4; i++)
        l[i] = s[i].x * w2.x + s[i].y * w2.y + s[i].z * w2.z + s[i].w * w2.w;

#pragma unroll
    for (int off = 16; off; off >>= 1) {
        base += __shfl_xor_sync(0xffffffffu, base, off);
#pragma unroll
        for (int i = 0; i < 4; i++) l[i] += __shfl_xor_sync(0xffffffffu, l[i], off);
    }

    float b = attn_b[d];
    float mx = -1e30f;
#pragma unroll
    for (int i = 0; i < 4; i++) {
        float v = base + l[i] + b;
        l[i] = v > 0.f ? v : 0.01f * v;
        mx = fmaxf(mx, l[i]);
    }
    float se = 0.f;
#pragma unroll
    for (int i = 0; i < 4; i++) { l[i] = __expf(l[i] - mx); se += l[i]; }
    float inv = 1.f / se;

    float4 o = make_float4(0.f, 0.f, 0.f, 0.f);
#pragma unroll
    for (int i = 0; i < 4; i++) {
        float wi = l[i] * inv;
        o.x += wi * s[i].x; o.y += wi * s[i].y; o.z += wi * s[i].z; o.w += wi * s[i].w;
    }
    *(float4*)(out + ((size_t)d * N + n) * DD + lane * 4) = o;
}

// ---------------------------------------------------------------------------
extern "C" void kernel_launch(void* const* d_in, const int* in_sizes, int n_in,
                              void* d_out, int out_size)
{
    const float* xs[3]   = {(const float*)d_in[0], (const float*)d_in[1], (const float*)d_in[2]};
    const float* Wih_c   = (const float*)d_in[3];
    const float* Whh_c   = (const float*)d_in[4];
    const float* bih_c   = (const float*)d_in[5];
    const float* bhh_c   = (const float*)d_in[6];
    const float* Wih_n   = (const float*)d_in[7];
    const float* Whh_n   = (const float*)d_in[8];
    const float* bih_n   = (const float*)d_in[9];
    const float* bhh_n   = (const float*)d_in[10];
    const float* attn_w  = (const float*)d_in[11];
    const float* attn_b  = (const float*)d_in[12];
    const int*   nbr     = (const int*)d_in[13];
    float* out = (float*)d_out;

    const int N = in_sizes[0] / (3 * DD);   // 30000

    float *content, *neigh, *bsum;
    unsigned short *gxc, *gxn;
    uint32_t* bp;
    cudaGetSymbolAddress((void**)&gxc,     g_gxc);
    cudaGetSymbolAddress((void**)&gxn,     g_gxn);
    cudaGetSymbolAddress((void**)&content, g_content);
    cudaGetSymbolAddress((void**)&neigh,   g_neigh);
    cudaGetSymbolAddress((void**)&bp,      g_bp);
    cudaGetSymbolAddress((void**)&bsum,    g_bsum);

    cudaFuncSetAttribute(gemm_tc,    cudaFuncAttributeMaxDynamicSharedMemorySize, GT_SMEM);
    cudaFuncSetAttribute(bilstm_mma, cudaFuncAttributeMaxDynamicSharedMemorySize, MM_SMEM);

    const int nt = (N + 63) / 64;
    const size_t cslab = (size_t)N * 3 * ROW;   // content slab stride (halves)

    // Stage 0: pack input-projection weights into fragment-native split-bf16
    prep_weights<<<4, 256>>>(Wih_c, bih_c, bhh_c, Wih_n, bih_n, bhh_n);

    // Stage A: 3 content input projections (shared weights, set 0) into slabs
    for (int s = 0; s < 3; s++)
        gemm_tc<<<(3 * N + 63) / 64, 512, GT_SMEM>>>(
            xs[s], bp, bsum, (__half*)(gxc + s * cslab), 3 * N);

    // Stage B: all 3 content bi-LSTMs in ONE launch (grid z = s)
    bilstm_mma<<<dim3(nt, 2, 3), 256, MM_SMEM>>>(
        (const __half*)gxc, nullptr, Whh_c, content, N, 3);

    // Stage C: neighbor gate pre-activations per source type (sets 1..3)
    for (int s = 0; s < 3; s++)
        gemm_tc<<<nt, 512, GT_SMEM>>>(
            content + (size_t)s * N * DD,
            bp + (size_t)(s + 1) * 65536,
            bsum + (size_t)(s + 1) * 512,
            (__half*)(gxn + (size_t)s * N * ROW), N);

    // Stage D: 9 neighbor bi-LSTM reductions (fp16 packed gathers)
    bilstm_mma<<<dim3(nt, 2, 9), 256, MM_SMEM>>>(
        (const __half*)gxn, nbr, Whh_n, neigh, N, 10);

    // Stage E: attention fusion
    attn_fuse<<<(3 * N + 7) / 8, 256>>>(content, neigh, attn_w, attn_b, out, N);
}